// round 6
// baseline (speedup 1.0000x reference)
#include <cuda_runtime.h>

#define IN_CH  128
#define K_HOPS 3
#define MAX_N  10240
#define MAX_E  330000

#define TMG   32                 // nodes per block in fused kernel
#define AROW  388                // 384 + 4 pad (float4-aligned, kills LDS bank conflicts)

// Scratch (__device__ globals: allocation-guard-safe)
__device__ float4 g_packed[MAX_E];      // {x0,x1,x2, bits(dst)} sorted by src
__device__ int    g_cnt[MAX_N + 1];
__device__ int    g_off[MAX_N + 1];
__device__ int    g_cur[MAX_N];
__device__ int    g_is64;

// ---------------------------------------------------------------------------
// Kernel 1: zero counts + detect edge_index dtype (JAX may emit int32 even
// though reference asks for int64; packed int32 pairs read as int64 are
// out-of-range almost surely over 64 samples).
// ---------------------------------------------------------------------------
__global__ void init_kernel(const void* ei, int E, int N) {
    int i = blockIdx.x * blockDim.x + threadIdx.x;
    if (i <= N) g_cnt[i] = 0;
    if (i == 0) {
        const long long* p64 = (const long long*)ei;
        int ok = 1;
        int cnt = (E < 64) ? E : 64;
        for (int j = 0; j < cnt; j++) {
            long long v = p64[j];
            if (v < 0 || v >= (long long)N) { ok = 0; break; }
        }
        g_is64 = ok;
    }
}

// ---------------------------------------------------------------------------
// Kernel 2: histogram of src.  4 edges per thread for MLP.
// ---------------------------------------------------------------------------
__global__ __launch_bounds__(256) void count_kernel(const void* __restrict__ ei,
                                                    int E, int N) {
    int e0 = (blockIdx.x * blockDim.x + threadIdx.x) * 4;
    if (e0 >= E) return;
    int s[4];
    if (g_is64) {
        const long long* p = (const long long*)ei;
        #pragma unroll
        for (int j = 0; j < 4; j++) s[j] = (e0 + j < E) ? (int)__ldg(p + e0 + j) : -1;
    } else {
        const int* p = (const int*)ei;
        if (e0 + 3 < E) {
            int4 v = __ldg(reinterpret_cast<const int4*>(p + e0));
            s[0] = v.x; s[1] = v.y; s[2] = v.z; s[3] = v.w;
        } else {
            #pragma unroll
            for (int j = 0; j < 4; j++) s[j] = (e0 + j < E) ? __ldg(p + e0 + j) : -1;
        }
    }
    #pragma unroll
    for (int j = 0; j < 4; j++)
        if ((unsigned)s[j] < (unsigned)N) atomicAdd(&g_cnt[s[j]], 1);
}

// ---------------------------------------------------------------------------
// Kernel 3: exclusive scan (single block) -> offsets + cursors
// ---------------------------------------------------------------------------
__global__ __launch_bounds__(1024) void scan_kernel(int N) {
    __shared__ int part[1024];
    int t = threadIdx.x;
    int chunk = (N + 1023) / 1024;
    int b0 = t * chunk;
    int b1 = b0 + chunk; if (b1 > N) b1 = N;
    int s = 0;
    for (int i = b0; i < b1; i++) s += g_cnt[i];
    part[t] = s;
    __syncthreads();
    for (int off = 1; off < 1024; off <<= 1) {
        int add = (t >= off) ? part[t - off] : 0;
        __syncthreads();
        part[t] += add;
        __syncthreads();
    }
    int run = part[t] - s;
    for (int i = b0; i < b1; i++) {
        g_off[i] = run;
        g_cur[i] = run;
        run += g_cnt[i];
    }
    if (t == 1023) g_off[N] = part[1023];
}

// ---------------------------------------------------------------------------
// Kernel 4: permute edges into src-sorted packed records.  4 edges/thread.
// ---------------------------------------------------------------------------
__global__ __launch_bounds__(256) void permute_kernel(const void* __restrict__ ei,
                                                      const float* __restrict__ X,
                                                      int E, int N) {
    int e0 = (blockIdx.x * blockDim.x + threadIdx.x) * 4;
    if (e0 >= E) return;

    int s[4], d[4];
    if (g_is64) {
        const long long* p = (const long long*)ei;
        #pragma unroll
        for (int j = 0; j < 4; j++) {
            s[j] = (e0 + j < E) ? (int)__ldg(p + e0 + j) : -1;
            d[j] = (e0 + j < E) ? (int)__ldg(p + (size_t)E + e0 + j) : -1;
        }
    } else {
        const int* p = (const int*)ei;
        if (e0 + 3 < E) {
            int4 vs = __ldg(reinterpret_cast<const int4*>(p + e0));
            int4 vd = __ldg(reinterpret_cast<const int4*>(p + E + e0));
            s[0] = vs.x; s[1] = vs.y; s[2] = vs.z; s[3] = vs.w;
            d[0] = vd.x; d[1] = vd.y; d[2] = vd.z; d[3] = vd.w;
        } else {
            #pragma unroll
            for (int j = 0; j < 4; j++) {
                s[j] = (e0 + j < E) ? __ldg(p + e0 + j) : -1;
                d[j] = (e0 + j < E) ? __ldg(p + E + e0 + j) : -1;
            }
        }
    }

    // X for 4 edges: 12 consecutive floats (aligned when full quad)
    float xv[12];
    if (e0 + 3 < E) {
        const float4* Xp = reinterpret_cast<const float4*>(X + (size_t)e0 * 3);
        float4 v0 = __ldg(Xp), v1 = __ldg(Xp + 1), v2 = __ldg(Xp + 2);
        xv[0]=v0.x; xv[1]=v0.y; xv[2]=v0.z; xv[3]=v0.w;
        xv[4]=v1.x; xv[5]=v1.y; xv[6]=v1.z; xv[7]=v1.w;
        xv[8]=v2.x; xv[9]=v2.y; xv[10]=v2.z; xv[11]=v2.w;
    } else {
        #pragma unroll
        for (int j = 0; j < 12; j++)
            xv[j] = (e0 + j / 3 < E) ? __ldg(X + (size_t)e0 * 3 + j) : 0.f;
    }

    int pos[4];
    #pragma unroll
    for (int j = 0; j < 4; j++)
        pos[j] = ((unsigned)s[j] < (unsigned)N) ? atomicAdd(&g_cur[s[j]], 1) : -1;
    #pragma unroll
    for (int j = 0; j < 4; j++)
        if (pos[j] >= 0 && (unsigned)d[j] < (unsigned)N)
            g_packed[pos[j]] = make_float4(xv[j*3], xv[j*3+1], xv[j*3+2],
                                           __int_as_float(d[j]));
}

// ---------------------------------------------------------------------------
// Kernel 5 (fused): gather-aggregate into smem, then per-hop GEMM + max + bias.
//   sA[nn][k*128+i] = sum_{e in CSR[n0+nn]} X[e,k] * h[dst[e], i]
//   out[n,o] = max_k( sum_i sA[n][k*128+i] * W[k,i,o] ) + bias[o]
// 256 threads: gather = 8 warps x 4 nodes each; GEMM thread tile = 4n x 4o.
// Dynamic smem: sA 32*388*4 = 49664 B, sW 64*128*4 = 32768 B -> 82432 B.
// ---------------------------------------------------------------------------
__global__ __launch_bounds__(256, 2) void fused_kernel(
    const float* __restrict__ h,
    const float* __restrict__ W,     // [3][128][128]
    const float* __restrict__ bias,  // [128]
    float* __restrict__ out,         // [N][128]
    int N)
{
    extern __shared__ float smem[];
    float* sA = smem;                // [TMG][AROW]
    float* sW = smem + TMG * AROW;   // [64][128]

    const int tid  = threadIdx.x;
    const int lane = tid & 31;
    const int warp = tid >> 5;
    const int n0   = blockIdx.x * TMG;

    // ---- gather phase: warp w handles nodes w*4 .. w*4+3 ----
    #pragma unroll
    for (int j = 0; j < 4; j++) {
        int nn   = warp * 4 + j;
        int node = n0 + nn;
        float4 a0 = make_float4(0.f, 0.f, 0.f, 0.f);
        float4 a1 = a0, a2 = a0;
        if (node < N) {
            int beg = __ldg(&g_off[node]);
            int end = __ldg(&g_off[node + 1]);
            int e = beg;
            for (; e + 1 < end; e += 2) {
                float4 p0 = __ldg(&g_packed[e]);
                float4 p1 = __ldg(&g_packed[e + 1]);
                int d0 = __float_as_int(p0.w);
                int d1 = __float_as_int(p1.w);
                float4 h0 = __ldg(reinterpret_cast<const float4*>(h + (size_t)d0 * IN_CH) + lane);
                float4 h1 = __ldg(reinterpret_cast<const float4*>(h + (size_t)d1 * IN_CH) + lane);
                a0.x += p0.x*h0.x; a0.y += p0.x*h0.y; a0.z += p0.x*h0.z; a0.w += p0.x*h0.w;
                a1.x += p0.y*h0.x; a1.y += p0.y*h0.y; a1.z += p0.y*h0.z; a1.w += p0.y*h0.w;
                a2.x += p0.z*h0.x; a2.y += p0.z*h0.y; a2.z += p0.z*h0.z; a2.w += p0.z*h0.w;
                a0.x += p1.x*h1.x; a0.y += p1.x*h1.y; a0.z += p1.x*h1.z; a0.w += p1.x*h1.w;
                a1.x += p1.y*h1.x; a1.y += p1.y*h1.y; a1.z += p1.y*h1.z; a1.w += p1.y*h1.w;
                a2.x += p1.z*h1.x; a2.y += p1.z*h1.y; a2.z += p1.z*h1.z; a2.w += p1.z*h1.w;
            }
            if (e < end) {
                float4 p0 = __ldg(&g_packed[e]);
                int d0 = __float_as_int(p0.w);
                float4 h0 = __ldg(reinterpret_cast<const float4*>(h + (size_t)d0 * IN_CH) + lane);
                a0.x += p0.x*h0.x; a0.y += p0.x*h0.y; a0.z += p0.x*h0.z; a0.w += p0.x*h0.w;
                a1.x += p0.y*h0.x; a1.y += p0.y*h0.y; a1.z += p0.y*h0.z; a1.w += p0.y*h0.w;
                a2.x += p0.z*h0.x; a2.y += p0.z*h0.y; a2.z += p0.z*h0.z; a2.w += p0.z*h0.w;
            }
        }
        float* dst = sA + nn * AROW;
        reinterpret_cast<float4*>(dst)[lane]       = a0;
        reinterpret_cast<float4*>(dst + 128)[lane] = a1;
        reinterpret_cast<float4*>(dst + 256)[lane] = a2;
    }

    // ---- GEMM phase ----
    const int to = lane;        // o = to*4 .. +3
    const int tn = warp;        // n = n0 + tn*4 .. +3

    float M[4][4];
    #pragma unroll
    for (int j = 0; j < 4; j++)
        #pragma unroll
        for (int q = 0; q < 4; q++) M[j][q] = -3.0e38f;

    for (int k = 0; k < K_HOPS; k++) {
        float C[4][4];
        #pragma unroll
        for (int j = 0; j < 4; j++)
            #pragma unroll
            for (int q = 0; q < 4; q++) C[j][q] = 0.f;

        #pragma unroll
        for (int c = 0; c < 2; c++) {
            __syncthreads();   // sA ready (first) / prior sW chunk consumed
            {
                const float4* Wg = reinterpret_cast<const float4*>(
                    W + ((size_t)k * IN_CH + c * 64) * IN_CH);
                float4* sW4 = reinterpret_cast<float4*>(sW);
                #pragma unroll
                for (int r = 0; r < 8; r++)
                    sW4[tid + r * 256] = __ldg(Wg + tid + r * 256);
            }
            __syncthreads();

            const float* aBase = sA + tn * 4 * AROW + k * IN_CH + c * 64;
            #pragma unroll 8
            for (int i = 0; i < 64; i++) {
                float4 b = *reinterpret_cast<const float4*>(&sW[i * IN_CH + to * 4]);
                float a0v = aBase[i];
                float a1v = aBase[AROW + i];
                float a2v = aBase[2 * AROW + i];
                float a3v = aBase[3 * AROW + i];
                C[0][0] += a0v*b.x; C[0][1] += a0v*b.y; C[0][2] += a0v*b.z; C[0][3] += a0v*b.w;
                C[1][0] += a1v*b.x; C[1][1] += a1v*b.y; C[1][2] += a1v*b.z; C[1][3] += a1v*b.w;
                C[2][0] += a2v*b.x; C[2][1] += a2v*b.y; C[2][2] += a2v*b.z; C[2][3] += a2v*b.w;
                C[3][0] += a3v*b.x; C[3][1] += a3v*b.y; C[3][2] += a3v*b.z; C[3][3] += a3v*b.w;
            }
        }

        #pragma unroll
        for (int j = 0; j < 4; j++)
            #pragma unroll
            for (int q = 0; q < 4; q++)
                M[j][q] = fmaxf(M[j][q], C[j][q]);
    }

    float4 bv = __ldg(reinterpret_cast<const float4*>(bias) + to);
    #pragma unroll
    for (int j = 0; j < 4; j++) {
        int node = n0 + tn * 4 + j;
        if (node < N) {
            float4 o;
            o.x = M[j][0] + bv.x;
            o.y = M[j][1] + bv.y;
            o.z = M[j][2] + bv.z;
            o.w = M[j][3] + bv.w;
            reinterpret_cast<float4*>(out + (size_t)node * IN_CH)[to] = o;
        }
    }
}

// ---------------------------------------------------------------------------
// Launch.  Inputs (metadata order): h[f32 N*128], X[f32 E*3],
// edge_index[2*E, int32 OR int64], batch_node[f32 N] (unused),
// weight[f32 3*128*128], bias[f32 128].  Output: f32 [N][128].
// ---------------------------------------------------------------------------
extern "C" void kernel_launch(void* const* d_in, const int* in_sizes, int n_in,
                              void* d_out, int out_size) {
    const float* h    = (const float*)d_in[0];
    const float* X    = (const float*)d_in[1];
    const void*  ei   = d_in[2];
    const float* W    = (const float*)d_in[4];
    const float* bias = (const float*)d_in[5];
    float*       out  = (float*)d_out;

    int N = in_sizes[0] / IN_CH;
    int E = in_sizes[1] / K_HOPS;

    const int SMEM_BYTES = (TMG * AROW + 64 * IN_CH) * (int)sizeof(float);  // 82432
    static int smem_set = 0;
    if (!smem_set) {
        cudaFuncSetAttribute(fused_kernel,
                             cudaFuncAttributeMaxDynamicSharedMemorySize, SMEM_BYTES);
        smem_set = 1;
    }

    init_kernel<<<(N + 1 + 255) / 256, 256>>>(ei, E, N);
    count_kernel<<<(E / 4 + 255) / 256, 256>>>(ei, E, N);
    scan_kernel<<<1, 1024>>>(N);
    permute_kernel<<<(E / 4 + 255) / 256, 256>>>(ei, X, E, N);
    fused_kernel<<<(N + TMG - 1) / TMG, 256, SMEM_BYTES>>>(h, W, bias, out, N);
}

// round 7
// speedup vs baseline: 1.4474x; 1.4474x over previous
#include <cuda_runtime.h>

#define IN_CH  128
#define K_HOPS 3
#define MAX_N  10240
#define MAX_E  330000

#define TN     72          // nodes per GEMM block -> 139 blocks (single wave, 148 SMs)

// Scratch (__device__ globals: allocation-guard-safe)
__device__ float  g_agg[(size_t)MAX_N * K_HOPS * IN_CH];   // [n][k][c] 15.7 MB
__device__ float4 g_packed[MAX_E];      // {x0,x1,x2, bits(dst)} sorted by src
__device__ int    g_rank[MAX_E];        // rank of edge within its src segment
__device__ int    g_cnt[MAX_N + 1];
__device__ int    g_off[MAX_N + 1];
__device__ int    g_is64;

// ---------------------------------------------------------------------------
// Kernel 1: zero counts + detect edge_index dtype (JAX may emit int32 even
// though the reference asks for int64; int32 pairs read as int64 are
// out-of-range almost surely across 64 samples).
// ---------------------------------------------------------------------------
__global__ void init_kernel(const void* ei, int E, int N) {
    int i = blockIdx.x * blockDim.x + threadIdx.x;
    if (i <= N) g_cnt[i] = 0;
    if (i == 0) {
        const long long* p64 = (const long long*)ei;
        int ok = 1;
        int cnt = (E < 64) ? E : 64;
        for (int j = 0; j < cnt; j++) {
            long long v = p64[j];
            if (v < 0 || v >= (long long)N) { ok = 0; break; }
        }
        g_is64 = ok;
    }
}

// ---------------------------------------------------------------------------
// Kernel 2: histogram of src + per-edge rank (moves the atomic out of permute)
// ---------------------------------------------------------------------------
__global__ __launch_bounds__(256) void count_kernel(const void* __restrict__ ei,
                                                    int E, int N) {
    int e = blockIdx.x * blockDim.x + threadIdx.x;
    if (e >= E) return;
    int src = g_is64 ? (int)__ldg((const long long*)ei + e)
                     : __ldg((const int*)ei + e);
    if ((unsigned)src < (unsigned)N)
        g_rank[e] = atomicAdd(&g_cnt[src], 1);
}

// ---------------------------------------------------------------------------
// Kernel 3: exclusive scan (single block) -> offsets
// ---------------------------------------------------------------------------
__global__ __launch_bounds__(1024) void scan_kernel(int N) {
    __shared__ int part[1024];
    int t = threadIdx.x;
    int chunk = (N + 1023) / 1024;
    int b0 = t * chunk;
    int b1 = b0 + chunk; if (b1 > N) b1 = N;
    int s = 0;
    for (int i = b0; i < b1; i++) s += g_cnt[i];
    part[t] = s;
    __syncthreads();
    for (int off = 1; off < 1024; off <<= 1) {
        int add = (t >= off) ? part[t - off] : 0;
        __syncthreads();
        part[t] += add;
        __syncthreads();
    }
    int run = part[t] - s;
    for (int i = b0; i < b1; i++) {
        g_off[i] = run;
        run += g_cnt[i];
    }
    if (t == 1023) g_off[N] = part[1023];
}

// ---------------------------------------------------------------------------
// Kernel 4: permute edges into src-sorted packed records.  No atomics:
// pos = off[src] + rank[e].  All loads independent -> latency-hidden.
// ---------------------------------------------------------------------------
__global__ __launch_bounds__(256) void permute_kernel(const void* __restrict__ ei,
                                                      const float* __restrict__ X,
                                                      int E, int N) {
    int e = blockIdx.x * blockDim.x + threadIdx.x;
    if (e >= E) return;
    int src, dst;
    if (g_is64) {
        const long long* p = (const long long*)ei;
        src = (int)__ldg(p + e);
        dst = (int)__ldg(p + (size_t)E + e);
    } else {
        const int* p = (const int*)ei;
        src = __ldg(p + e);
        dst = __ldg(p + (size_t)E + e);
    }
    if ((unsigned)src >= (unsigned)N || (unsigned)dst >= (unsigned)N) return;
    float x0 = __ldg(X + (size_t)e * 3 + 0);
    float x1 = __ldg(X + (size_t)e * 3 + 1);
    float x2 = __ldg(X + (size_t)e * 3 + 2);
    int pos = __ldg(&g_off[src]) + __ldg(&g_rank[e]);
    g_packed[pos] = make_float4(x0, x1, x2, __int_as_float(dst));
}

// ---------------------------------------------------------------------------
// Kernel 5: gather-aggregate.  One warp per node; lane owns 4 channels.
// 4-edge unroll for MLP.  Writes every node -> no zero pass needed.
// ---------------------------------------------------------------------------
__global__ __launch_bounds__(256) void gather_kernel(
    const float* __restrict__ h, int N) {
    int w    = (blockIdx.x * blockDim.x + threadIdx.x) >> 5;   // node
    int lane = threadIdx.x & 31;
    if (w >= N) return;

    int beg = __ldg(&g_off[w]);
    int end = __ldg(&g_off[w + 1]);

    float4 a0 = make_float4(0.f, 0.f, 0.f, 0.f);
    float4 a1 = a0, a2 = a0;

    int e = beg;
    for (; e + 3 < end; e += 4) {
        float4 p[4];
        #pragma unroll
        for (int j = 0; j < 4; j++) p[j] = __ldg(&g_packed[e + j]);
        float4 hv[4];
        #pragma unroll
        for (int j = 0; j < 4; j++) {
            int d = __float_as_int(p[j].w);
            hv[j] = __ldg(reinterpret_cast<const float4*>(h + (size_t)d * IN_CH) + lane);
        }
        #pragma unroll
        for (int j = 0; j < 4; j++) {
            a0.x += p[j].x*hv[j].x; a0.y += p[j].x*hv[j].y; a0.z += p[j].x*hv[j].z; a0.w += p[j].x*hv[j].w;
            a1.x += p[j].y*hv[j].x; a1.y += p[j].y*hv[j].y; a1.z += p[j].y*hv[j].z; a1.w += p[j].y*hv[j].w;
            a2.x += p[j].z*hv[j].x; a2.y += p[j].z*hv[j].y; a2.z += p[j].z*hv[j].z; a2.w += p[j].z*hv[j].w;
        }
    }
    for (; e < end; e++) {
        float4 p0 = __ldg(&g_packed[e]);
        int d0 = __float_as_int(p0.w);
        float4 h0 = __ldg(reinterpret_cast<const float4*>(h + (size_t)d0 * IN_CH) + lane);
        a0.x += p0.x*h0.x; a0.y += p0.x*h0.y; a0.z += p0.x*h0.z; a0.w += p0.x*h0.w;
        a1.x += p0.y*h0.x; a1.y += p0.y*h0.y; a1.z += p0.y*h0.z; a1.w += p0.y*h0.w;
        a2.x += p0.z*h0.x; a2.y += p0.z*h0.y; a2.z += p0.z*h0.z; a2.w += p0.z*h0.w;
    }

    float4* base = reinterpret_cast<float4*>(g_agg + (size_t)w * (K_HOPS * IN_CH));
    base[lane]      = a0;
    base[32 + lane] = a1;
    base[64 + lane] = a2;
}

// ---------------------------------------------------------------------------
// Kernel 6: fused per-hop GEMM + max over hops + bias.
//   out[n,o] = max_k( sum_i agg[n,k,i] * W[k,i,o] ) + bias[o]
// Block: 72 nodes x 128 outs, 256 threads -> 139 blocks = single balanced wave.
// Per hop: sA = transposed agg slice [i][node] (128x72), sW = full W hop
// (128x128).  Dynamic smem 100 KB.  Thread tile 9n x 4o.
// ---------------------------------------------------------------------------
__global__ __launch_bounds__(256, 1) void gemm_max_bias_kernel(
    const float* __restrict__ W,     // [3][128][128]
    const float* __restrict__ bias,  // [128]
    float* __restrict__ out,         // [N][128]
    int N)
{
    extern __shared__ float smem[];
    float* sA = smem;                  // [128][TN]
    float* sW = smem + IN_CH * TN;     // [128][128]

    const int tid  = threadIdx.x;
    const int to   = tid & 31;     // o = to*4 .. +3
    const int tw   = tid >> 5;     // warp: nodes tw*9 .. +8
    const int n0   = blockIdx.x * TN;

    float M[9][4];
    #pragma unroll
    for (int j = 0; j < 9; j++)
        #pragma unroll
        for (int q = 0; q < 4; q++) M[j][q] = -3.0e38f;

    for (int k = 0; k < K_HOPS; k++) {
        __syncthreads();   // previous hop's readers done

        // Stage sA: 72 nodes x 128 i, transposed.  2304 float4 loads.
        #pragma unroll
        for (int r = 0; r < 9; r++) {
            int idx = tid + r * 256;      // 0..2303
            int nn  = idx % TN;
            int ig  = idx / TN;           // 0..31
            int node = n0 + nn;
            float4 v = make_float4(0.f, 0.f, 0.f, 0.f);
            if (node < N)
                v = __ldg(reinterpret_cast<const float4*>(
                        g_agg + (size_t)node * (K_HOPS * IN_CH) + k * IN_CH + ig * 4));
            sA[(ig * 4 + 0) * TN + nn] = v.x;
            sA[(ig * 4 + 1) * TN + nn] = v.y;
            sA[(ig * 4 + 2) * TN + nn] = v.z;
            sA[(ig * 4 + 3) * TN + nn] = v.w;
        }
        // Stage sW: full hop, 4096 float4 loads.
        {
            const float4* Wg = reinterpret_cast<const float4*>(W + (size_t)k * IN_CH * IN_CH);
            float4* sW4 = reinterpret_cast<float4*>(sW);
            #pragma unroll
            for (int r = 0; r < 16; r++)
                sW4[tid + r * 256] = __ldg(Wg + tid + r * 256);
        }
        __syncthreads();

        float C[9][4];
        #pragma unroll
        for (int j = 0; j < 9; j++)
            #pragma unroll
            for (int q = 0; q < 4; q++) C[j][q] = 0.f;

        const float* aBase = sA + tw * 9;
        #pragma unroll 8
        for (int i = 0; i < IN_CH; i++) {
            float4 b = *reinterpret_cast<const float4*>(&sW[i * IN_CH + to * 4]);
            float a[9];
            #pragma unroll
            for (int j = 0; j < 9; j++) a[j] = aBase[i * TN + j];
            #pragma unroll
            for (int j = 0; j < 9; j++) {
                C[j][0] += a[j] * b.x;
                C[j][1] += a[j] * b.y;
                C[j][2] += a[j] * b.z;
                C[j][3] += a[j] * b.w;
            }
        }

        #pragma unroll
        for (int j = 0; j < 9; j++)
            #pragma unroll
            for (int q = 0; q < 4; q++)
                M[j][q] = fmaxf(M[j][q], C[j][q]);
    }

    float4 bv = __ldg(reinterpret_cast<const float4*>(bias) + to);
    #pragma unroll
    for (int j = 0; j < 9; j++) {
        int node = n0 + tw * 9 + j;
        if (node < N) {
            float4 o;
            o.x = M[j][0] + bv.x;
            o.y = M[j][1] + bv.y;
            o.z = M[j][2] + bv.z;
            o.w = M[j][3] + bv.w;
            reinterpret_cast<float4*>(out + (size_t)node * IN_CH)[to] = o;
        }
    }
}

// ---------------------------------------------------------------------------
// Launch.  Inputs (metadata order): h[f32 N*128], X[f32 E*3],
// edge_index[2*E, int32 OR int64], batch_node[f32 N] (unused),
// weight[f32 3*128*128], bias[f32 128].  Output: f32 [N][128].
// ---------------------------------------------------------------------------
extern "C" void kernel_launch(void* const* d_in, const int* in_sizes, int n_in,
                              void* d_out, int out_size) {
    const float* h    = (const float*)d_in[0];
    const float* X    = (const float*)d_in[1];
    const void*  ei   = d_in[2];
    const float* W    = (const float*)d_in[4];
    const float* bias = (const float*)d_in[5];
    float*       out  = (float*)d_out;

    int N = in_sizes[0] / IN_CH;
    int E = in_sizes[1] / K_HOPS;

    const int SMEM_BYTES = (IN_CH * TN + IN_CH * IN_CH) * (int)sizeof(float);  // 102400
    static int smem_set = 0;
    if (!smem_set) {
        cudaFuncSetAttribute(gemm_max_bias_kernel,
                             cudaFuncAttributeMaxDynamicSharedMemorySize, SMEM_BYTES);
        smem_set = 1;
    }

    init_kernel<<<(N + 1 + 255) / 256, 256>>>(ei, E, N);
    count_kernel<<<(E + 255) / 256, 256>>>(ei, E, N);
    scan_kernel<<<1, 1024>>>(N);
    permute_kernel<<<(E + 255) / 256, 256>>>(ei, X, E, N);
    gather_kernel<<<(N + 7) / 8, 256>>>(h, N);                      // warp per node
    gemm_max_bias_kernel<<<(N + TN - 1) / TN, 256, SMEM_BYTES>>>(W, bias, out, N);
}

// round 9
// speedup vs baseline: 1.6319x; 1.1275x over previous
#include <cuda_runtime.h>
#include <cstdint>

#define IN_CH  128
#define K_HOPS 3
#define MAX_N  10240
#define MAX_E  330000

#define TN     80          // nodes per GEMM block -> 125 blocks (single wave)

// Scratch (__device__ globals: allocation-guard-safe)
__device__ float  g_agg[(size_t)MAX_N * K_HOPS * IN_CH];   // [n][k][c] 15.7 MB
__device__ float4 g_packed[MAX_E];      // {x0,x1,x2, bits(dst)} sorted by src
__device__ int    g_rank[MAX_E];
__device__ int    g_cnt[MAX_N + 1];
__device__ int    g_off[MAX_N + 1];
__device__ int    g_is64;

// ---------------------------------------------------------------------------
// f32x2 packed helpers (PTX ISA 8.6, sm_100+; NOT an 'a'-suffix feature)
// ---------------------------------------------------------------------------
__device__ __forceinline__ void ffma2(uint64_t& c, uint64_t a, uint64_t b) {
    asm("fma.rn.f32x2 %0, %1, %2, %0;" : "+l"(c) : "l"(a), "l"(b));
}
__device__ __forceinline__ uint64_t bcast2(float v) {
    uint64_t r;
    asm("mov.b64 %0, {%1, %1};" : "=l"(r) : "r"(__float_as_uint(v)));
    return r;
}

// ---------------------------------------------------------------------------
// Kernel 1: zero counts + detect edge_index dtype (JAX may emit int32 even
// though the reference asks for int64).
// ---------------------------------------------------------------------------
__global__ void init_kernel(const void* ei, int E, int N) {
    int i = blockIdx.x * blockDim.x + threadIdx.x;
    if (i <= N) g_cnt[i] = 0;
    if (i == 0) {
        const long long* p64 = (const long long*)ei;
        int ok = 1;
        int cnt = (E < 64) ? E : 64;
        for (int j = 0; j < cnt; j++) {
            long long v = p64[j];
            if (v < 0 || v >= (long long)N) { ok = 0; break; }
        }
        g_is64 = ok;
    }
}

// ---------------------------------------------------------------------------
// Kernel 2: histogram of src + per-edge rank (atomic moved out of permute)
// ---------------------------------------------------------------------------
__global__ __launch_bounds__(256) void count_kernel(const void* __restrict__ ei,
                                                    int E, int N) {
    int e = blockIdx.x * blockDim.x + threadIdx.x;
    if (e >= E) return;
    int src = g_is64 ? (int)__ldg((const long long*)ei + e)
                     : __ldg((const int*)ei + e);
    if ((unsigned)src < (unsigned)N)
        g_rank[e] = atomicAdd(&g_cnt[src], 1);
}

// ---------------------------------------------------------------------------
// Kernel 3: exclusive scan (single block) -> offsets
// ---------------------------------------------------------------------------
__global__ __launch_bounds__(1024) void scan_kernel(int N) {
    __shared__ int part[1024];
    int t = threadIdx.x;
    int chunk = (N + 1023) / 1024;
    int b0 = t * chunk;
    int b1 = b0 + chunk; if (b1 > N) b1 = N;
    int s = 0;
    for (int i = b0; i < b1; i++) s += g_cnt[i];
    part[t] = s;
    __syncthreads();
    for (int off = 1; off < 1024; off <<= 1) {
        int add = (t >= off) ? part[t - off] : 0;
        __syncthreads();
        part[t] += add;
        __syncthreads();
    }
    int run = part[t] - s;
    for (int i = b0; i < b1; i++) { g_off[i] = run; run += g_cnt[i]; }
    if (t == 1023) g_off[N] = part[1023];
}

// ---------------------------------------------------------------------------
// Kernel 4: permute edges into src-sorted packed records (atomic-free)
// ---------------------------------------------------------------------------
__global__ __launch_bounds__(256) void permute_kernel(const void* __restrict__ ei,
                                                      const float* __restrict__ X,
                                                      int E, int N) {
    int e = blockIdx.x * blockDim.x + threadIdx.x;
    if (e >= E) return;
    int src, dst;
    if (g_is64) {
        const long long* p = (const long long*)ei;
        src = (int)__ldg(p + e);
        dst = (int)__ldg(p + (size_t)E + e);
    } else {
        const int* p = (const int*)ei;
        src = __ldg(p + e);
        dst = __ldg(p + (size_t)E + e);
    }
    if ((unsigned)src >= (unsigned)N || (unsigned)dst >= (unsigned)N) return;
    float x0 = __ldg(X + (size_t)e * 3 + 0);
    float x1 = __ldg(X + (size_t)e * 3 + 1);
    float x2 = __ldg(X + (size_t)e * 3 + 2);
    int pos = __ldg(&g_off[src]) + __ldg(&g_rank[e]);
    g_packed[pos] = make_float4(x0, x1, x2, __int_as_float(dst));
}

// ---------------------------------------------------------------------------
// Kernel 5: gather-aggregate.  One warp per node; lane owns 4 channels.
// 4-edge unroll for MLP.  Writes every node -> no zero pass needed.
// ---------------------------------------------------------------------------
__global__ __launch_bounds__(256) void gather_kernel(
    const float* __restrict__ h, int N) {
    int w    = (blockIdx.x * blockDim.x + threadIdx.x) >> 5;
    int lane = threadIdx.x & 31;
    if (w >= N) return;

    int beg = __ldg(&g_off[w]);
    int end = __ldg(&g_off[w + 1]);

    float4 a0 = make_float4(0.f, 0.f, 0.f, 0.f);
    float4 a1 = a0, a2 = a0;

    int e = beg;
    for (; e + 3 < end; e += 4) {
        float4 p[4];
        #pragma unroll
        for (int j = 0; j < 4; j++) p[j] = __ldg(&g_packed[e + j]);
        float4 hv[4];
        #pragma unroll
        for (int j = 0; j < 4; j++) {
            int d = __float_as_int(p[j].w);
            hv[j] = __ldg(reinterpret_cast<const float4*>(h + (size_t)d * IN_CH) + lane);
        }
        #pragma unroll
        for (int j = 0; j < 4; j++) {
            a0.x += p[j].x*hv[j].x; a0.y += p[j].x*hv[j].y; a0.z += p[j].x*hv[j].z; a0.w += p[j].x*hv[j].w;
            a1.x += p[j].y*hv[j].x; a1.y += p[j].y*hv[j].y; a1.z += p[j].y*hv[j].z; a1.w += p[j].y*hv[j].w;
            a2.x += p[j].z*hv[j].x; a2.y += p[j].z*hv[j].y; a2.z += p[j].z*hv[j].z; a2.w += p[j].z*hv[j].w;
        }
    }
    for (; e < end; e++) {
        float4 p0 = __ldg(&g_packed[e]);
        int d0 = __float_as_int(p0.w);
        float4 h0 = __ldg(reinterpret_cast<const float4*>(h + (size_t)d0 * IN_CH) + lane);
        a0.x += p0.x*h0.x; a0.y += p0.x*h0.y; a0.z += p0.x*h0.z; a0.w += p0.x*h0.w;
        a1.x += p0.y*h0.x; a1.y += p0.y*h0.y; a1.z += p0.y*h0.z; a1.w += p0.y*h0.w;
        a2.x += p0.z*h0.x; a2.y += p0.z*h0.y; a2.z += p0.z*h0.z; a2.w += p0.z*h0.w;
    }

    float4* base = reinterpret_cast<float4*>(g_agg + (size_t)w * (K_HOPS * IN_CH));
    base[lane]      = a0;
    base[32 + lane] = a1;
    base[64 + lane] = a2;
}

// ---------------------------------------------------------------------------
// Kernel 6: fused per-hop GEMM + max over hops + bias, f32x2 packed FMA.
//   out[n,o] = max_k( sum_i agg[n,k,i] * W[k,i,o] ) + bias[o]
// Block: 80 nodes x 128 outs, 256 threads -> 125 blocks = single wave.
// sA = transposed agg slice [i][node] (128x80): adjacent nodes contiguous,
// so an f32x2 a-operand is ONE 8-byte LDS (no packing).  sW = full W hop.
// Thread tile: 10 nodes (5 f32x2 pairs) x 4 outs = 20 FFMA2 per i.
// Dynamic smem 104 KB.
// ---------------------------------------------------------------------------
__global__ __launch_bounds__(256, 1) void gemm_max_bias_kernel(
    const float* __restrict__ W,     // [3][128][128]
    const float* __restrict__ bias,  // [128]
    float* __restrict__ out,         // [N][128]
    int N)
{
    extern __shared__ float smem[];
    float* sA = smem;                  // [128][TN]
    float* sW = smem + IN_CH * TN;     // [128][128]

    const int tid = threadIdx.x;
    const int to  = tid & 31;     // o = to*4 .. +3
    const int tw  = tid >> 5;     // warp: nodes tw*10 .. +9
    const int n0  = blockIdx.x * TN;

    float M[10][4];
    #pragma unroll
    for (int j = 0; j < 10; j++)
        #pragma unroll
        for (int q = 0; q < 4; q++) M[j][q] = -3.0e38f;

    for (int k = 0; k < K_HOPS; k++) {
        __syncthreads();   // previous hop's readers done

        // Stage sA: 80 nodes x 128 i, transposed.  2560 float4 loads.
        #pragma unroll
        for (int r = 0; r < 10; r++) {
            int idx = tid + r * 256;      // 0..2559
            int nn  = idx % TN;
            int ig  = idx / TN;           // 0..31
            int node = n0 + nn;
            float4 v = make_float4(0.f, 0.f, 0.f, 0.f);
            if (node < N)
                v = __ldg(reinterpret_cast<const float4*>(
                        g_agg + (size_t)node * (K_HOPS * IN_CH) + k * IN_CH + ig * 4));
            sA[(ig * 4 + 0) * TN + nn] = v.x;
            sA[(ig * 4 + 1) * TN + nn] = v.y;
            sA[(ig * 4 + 2) * TN + nn] = v.z;
            sA[(ig * 4 + 3) * TN + nn] = v.w;
        }
        // Stage sW: full hop, 4096 float4 loads.
        {
            const float4* Wg = reinterpret_cast<const float4*>(W + (size_t)k * IN_CH * IN_CH);
            float4* sW4 = reinterpret_cast<float4*>(sW);
            #pragma unroll
            for (int r = 0; r < 16; r++)
                sW4[tid + r * 256] = __ldg(Wg + tid + r * 256);
        }
        __syncthreads();

        uint64_t C[5][4];
        #pragma unroll
        for (int p = 0; p < 5; p++)
            #pragma unroll
            for (int q = 0; q < 4; q++) C[p][q] = 0ull;

        const float* aRow0 = sA + tw * 10;   // 40*tw bytes: 8B-aligned
        #pragma unroll 8
        for (int i = 0; i < IN_CH; i++) {
            const uint64_t* ap = reinterpret_cast<const uint64_t*>(aRow0 + i * TN);
            uint64_t a0 = ap[0], a1 = ap[1], a2 = ap[2], a3 = ap[3], a4 = ap[4];
            float4 b = *reinterpret_cast<const float4*>(&sW[i * IN_CH + to * 4]);
            uint64_t b0 = bcast2(b.x), b1 = bcast2(b.y), b2 = bcast2(b.z), b3 = bcast2(b.w);
            ffma2(C[0][0], a0, b0); ffma2(C[0][1], a0, b1); ffma2(C[0][2], a0, b2); ffma2(C[0][3], a0, b3);
            ffma2(C[1][0], a1, b0); ffma2(C[1][1], a1, b1); ffma2(C[1][2], a1, b2); ffma2(C[1][3], a1, b3);
            ffma2(C[2][0], a2, b0); ffma2(C[2][1], a2, b1); ffma2(C[2][2], a2, b2); ffma2(C[2][3], a2, b3);
            ffma2(C[3][0], a3, b0); ffma2(C[3][1], a3, b1); ffma2(C[3][2], a3, b2); ffma2(C[3][3], a3, b3);
            ffma2(C[4][0], a4, b0); ffma2(C[4][1], a4, b1); ffma2(C[4][2], a4, b2); ffma2(C[4][3], a4, b3);
        }

        // Fold packed pairs into running max (lo half = even node)
        #pragma unroll
        for (int p = 0; p < 5; p++)
            #pragma unroll
            for (int q = 0; q < 4; q++) {
                float lo = __uint_as_float((uint32_t)(C[p][q] & 0xFFFFFFFFull));
                float hi = __uint_as_float((uint32_t)(C[p][q] >> 32));
                M[2 * p][q]     = fmaxf(M[2 * p][q], lo);
                M[2 * p + 1][q] = fmaxf(M[2 * p + 1][q], hi);
            }
    }

    float4 bv = __ldg(reinterpret_cast<const float4*>(bias) + to);
    #pragma unroll
    for (int j = 0; j < 10; j++) {
        int node = n0 + tw * 10 + j;
        if (node < N) {
            float4 o;
            o.x = M[j][0] + bv.x;
            o.y = M[j][1] + bv.y;
            o.z = M[j][2] + bv.z;
            o.w = M[j][3] + bv.w;
            reinterpret_cast<float4*>(out + (size_t)node * IN_CH)[to] = o;
        }
    }
}

// ---------------------------------------------------------------------------
// Launch.  Inputs (metadata order): h[f32 N*128], X[f32 E*3],
// edge_index[2*E, int32 OR int64], batch_node[f32 N] (unused),
// weight[f32 3*128*128], bias[f32 128].  Output: f32 [N][128].
// ---------------------------------------------------------------------------
extern "C" void kernel_launch(void* const* d_in, const int* in_sizes, int n_in,
                              void* d_out, int out_size) {
    const float* h    = (const float*)d_in[0];
    const float* X    = (const float*)d_in[1];
    const void*  ei   = d_in[2];
    const float* W    = (const float*)d_in[4];
    const float* bias = (const float*)d_in[5];
    float*       out  = (float*)d_out;

    int N = in_sizes[0] / IN_CH;
    int E = in_sizes[1] / K_HOPS;

    const int SMEM_BYTES = (IN_CH * TN + IN_CH * IN_CH) * (int)sizeof(float);  // 106496
    static int smem_set = 0;
    if (!smem_set) {
        cudaFuncSetAttribute(gemm_max_bias_kernel,
                             cudaFuncAttributeMaxDynamicSharedMemorySize, SMEM_BYTES);
        smem_set = 1;
    }

    init_kernel<<<(N + 1 + 255) / 256, 256>>>(ei, E, N);
    count_kernel<<<(E + 255) / 256, 256>>>(ei, E, N);
    scan_kernel<<<1, 1024>>>(N);
    permute_kernel<<<(E + 255) / 256, 256>>>(ei, X, E, N);
    gather_kernel<<<(N + 7) / 8, 256>>>(h, N);                      // warp per node
    gemm_max_bias_kernel<<<(N + TN - 1) / TN, 256, SMEM_BYTES>>>(W, bias, out, N);
}